// round 1
// baseline (speedup 1.0000x reference)
#include <cuda_runtime.h>

#define FULL 0xffffffffu

constexpr int MAXV = 100000;
constexpr int MAXE = 1200000;
// C=64, M=8, O=64 fixed for this problem.

__device__ float g_xu[MAXV * 8];
__device__ float g_agg[(long long)MAXV * 512];
__device__ int   g_count[MAXV];
__device__ int   g_starts[MAXV];
__device__ int   g_cursor[MAXV];
__device__ int   g_partials[256];
__device__ int   g_pprefix[256];
__device__ int   g_sdst[MAXE];
__device__ float g_sw[MAXE];

// ---------------- counting sort of edges by src ----------------

__global__ void k_zero(int V) {
    int i = blockIdx.x * blockDim.x + threadIdx.x;
    if (i < V) g_count[i] = 0;
}

__global__ void k_hist(const int* __restrict__ src, int E) {
    int e = blockIdx.x * blockDim.x + threadIdx.x;
    if (e < E) atomicAdd(&g_count[src[e]], 1);
}

__global__ void k_scan_block(int V) {
    __shared__ int s[1024];
    int t = threadIdx.x;
    int i = blockIdx.x * 1024 + t;
    int v = (i < V) ? g_count[i] : 0;
    s[t] = v;
    __syncthreads();
    #pragma unroll
    for (int off = 1; off < 1024; off <<= 1) {
        int add = (t >= off) ? s[t - off] : 0;
        __syncthreads();
        s[t] += add;
        __syncthreads();
    }
    if (i < V) g_starts[i] = s[t] - v;           // exclusive within block
    if (t == 1023) g_partials[blockIdx.x] = s[1023];
}

__global__ void k_scan_partials(int nb) {
    if (threadIdx.x == 0) {
        int acc = 0;
        for (int i = 0; i < nb; i++) { g_pprefix[i] = acc; acc += g_partials[i]; }
    }
}

__global__ void k_scan_add(int V) {
    int t = threadIdx.x;
    int i = blockIdx.x * 1024 + t;
    if (i < V) {
        int s = g_starts[i] + g_pprefix[blockIdx.x];
        g_starts[i] = s;
        g_cursor[i] = s;
    }
}

__global__ void k_scatter(const int* __restrict__ src, const int* __restrict__ dst,
                          const float* __restrict__ w, int E) {
    int e = blockIdx.x * blockDim.x + threadIdx.x;
    if (e < E) {
        int p = atomicAdd(&g_cursor[src[e]], 1);
        g_sdst[p] = dst[e];
        g_sw[p]   = w[e];
    }
}

// ---------------- xu = data @ var_u  [V,8] ----------------

__global__ void k_xu(const float* __restrict__ data, const float* __restrict__ u, int V) {
    __shared__ float us[512];
    int t = threadIdx.x;
    us[t] = u[t];
    us[t + 256] = u[t + 256];
    __syncthreads();
    int v = blockIdx.x * 256 + t;
    if (v >= V) return;
    float s[8];
    #pragma unroll
    for (int j = 0; j < 8; j++) s[j] = 0.f;
    const float4* row = (const float4*)(data + (long long)v * 64);
    #pragma unroll
    for (int c4 = 0; c4 < 16; c4++) {
        float4 x = row[c4];
        float xs4[4] = {x.x, x.y, x.z, x.w};
        #pragma unroll
        for (int k = 0; k < 4; k++) {
            int c = c4 * 4 + k;
            #pragma unroll
            for (int j = 0; j < 8; j++) s[j] = fmaf(xs4[k], us[c * 8 + j], s[j]);
        }
    }
    #pragma unroll
    for (int j = 0; j < 8; j++) g_xu[v * 8 + j] = s[j];
}

// ---------------- per-vertex edge aggregation (warp per vertex, no atomics) ----------------
// acc[m][c] for c = lane*2, lane*2+1  -> 16 registers per lane

__global__ void k_edge(const float* __restrict__ data, const float* __restrict__ cvec, int V) {
    int gw   = (blockIdx.x * blockDim.x + threadIdx.x) >> 5;
    int lane = threadIdx.x & 31;
    if (gw >= V) return;
    int v = gw;

    float xsc = 0.f;
    if (lane < 8) xsc = g_xu[v * 8 + lane] + cvec[lane];

    int beg = g_starts[v];
    int deg = g_count[v];

    float acc[16];
    #pragma unroll
    for (int i = 0; i < 16; i++) acc[i] = 0.f;

    for (int t = 0; t < deg; t++) {
        int p = beg + t;
        int d = 0; float w = 0.f;
        if (lane == 0) { d = g_sdst[p]; w = g_sw[p]; }
        d = __shfl_sync(FULL, d, 0);
        w = __shfl_sync(FULL, w, 0);

        // softmax over M=8 on lanes 0..7 (xor-reduce stays within 8-groups)
        float logit = 0.f;
        if (lane < 8) logit = xsc - g_xu[d * 8 + lane];
        float mx = logit;
        mx = fmaxf(mx, __shfl_xor_sync(FULL, mx, 4));
        mx = fmaxf(mx, __shfl_xor_sync(FULL, mx, 2));
        mx = fmaxf(mx, __shfl_xor_sync(FULL, mx, 1));
        float ex = __expf(logit - mx);
        float sm = ex;
        sm += __shfl_xor_sync(FULL, sm, 4);
        sm += __shfl_xor_sync(FULL, sm, 2);
        sm += __shfl_xor_sync(FULL, sm, 1);
        float qw = __fdividef(ex, sm) * w;   // valid on lanes 0..7

        float2 xj = *(const float2*)(data + (long long)d * 64 + lane * 2);
        #pragma unroll
        for (int m = 0; m < 8; m++) {
            float qm = __shfl_sync(FULL, qw, m);
            acc[2 * m]     = fmaf(qm, xj.x, acc[2 * m]);
            acc[2 * m + 1] = fmaf(qm, xj.y, acc[2 * m + 1]);
        }
    }

    float* aggv = g_agg + (long long)v * 512;
    #pragma unroll
    for (int m = 0; m < 8; m++)
        *(float2*)(aggv + m * 64 + lane * 2) = make_float2(acc[2 * m], acc[2 * m + 1]);
}

// ---------------- out[V,64] = agg[V,512] @ Wflat[512,64] + b ----------------
// BM=128, BN=64 (full), BK=32, 256 threads, 8x4 microtile per thread.

__global__ void __launch_bounds__(256)
k_gemm(const float* __restrict__ W, const float* __restrict__ bias,
       float* __restrict__ out, int V) {
    __shared__ __align__(16) float As[32][132];   // transposed A tile [k][m], pad 4
    __shared__ __align__(16) float Bs[32][64];

    int tid = threadIdx.x;
    int tx = tid & 15;      // col group: 4 cols
    int ty = tid >> 4;      // row group: 8 rows
    int row0 = blockIdx.x * 128;

    float acc[8][4];
    #pragma unroll
    for (int i = 0; i < 8; i++)
        #pragma unroll
        for (int j = 0; j < 4; j++) acc[i][j] = 0.f;

    float4 bb = *(const float4*)(bias + tx * 4);

    for (int k0 = 0; k0 < 512; k0 += 32) {
        // A tile: 128 x 32 = 1024 float4, 4 per thread, transposed into smem
        #pragma unroll
        for (int ch = 0; ch < 4; ch++) {
            int f  = ch * 256 + tid;      // 0..1023
            int r  = f >> 3;              // 8 float4 per row
            int kq = f & 7;
            float4 a;
            int row = row0 + r;
            if (row < V) a = *(const float4*)(g_agg + (long long)row * 512 + k0 + kq * 4);
            else         a = make_float4(0.f, 0.f, 0.f, 0.f);
            As[kq * 4 + 0][r] = a.x;
            As[kq * 4 + 1][r] = a.y;
            As[kq * 4 + 2][r] = a.z;
            As[kq * 4 + 3][r] = a.w;
        }
        // B tile: 32 x 64 = 512 float4, 2 per thread
        #pragma unroll
        for (int ch = 0; ch < 2; ch++) {
            int f  = ch * 256 + tid;      // 0..511
            int kk = f >> 4;              // 16 float4 per row
            int n4 = f & 15;
            *(float4*)&Bs[kk][n4 * 4] = *(const float4*)(W + (k0 + kk) * 64 + n4 * 4);
        }
        __syncthreads();

        #pragma unroll
        for (int kk = 0; kk < 32; kk++) {
            float4 b0 = *(const float4*)&Bs[kk][tx * 4];
            float4 a0 = *(const float4*)&As[kk][ty * 8];
            float4 a1 = *(const float4*)&As[kk][ty * 8 + 4];
            float a[8] = {a0.x, a0.y, a0.z, a0.w, a1.x, a1.y, a1.z, a1.w};
            float b[4] = {b0.x, b0.y, b0.z, b0.w};
            #pragma unroll
            for (int i = 0; i < 8; i++)
                #pragma unroll
                for (int j = 0; j < 4; j++)
                    acc[i][j] = fmaf(a[i], b[j], acc[i][j]);
        }
        __syncthreads();
    }

    #pragma unroll
    for (int i = 0; i < 8; i++) {
        int row = row0 + ty * 8 + i;
        if (row < V) {
            float4 o = make_float4(acc[i][0] + bb.x, acc[i][1] + bb.y,
                                   acc[i][2] + bb.z, acc[i][3] + bb.w);
            *(float4*)(out + (long long)row * 64 + tx * 4) = o;
        }
    }
}

// ---------------- launch ----------------

extern "C" void kernel_launch(void* const* d_in, const int* in_sizes, int n_in,
                              void* d_out, int out_size) {
    const float* data = (const float*)d_in[0];
    const int*   esrc = (const int*)  d_in[1];
    const int*   edst = (const int*)  d_in[2];
    const float* ew   = (const float*)d_in[3];
    const float* vu   = (const float*)d_in[4];
    const float* vc   = (const float*)d_in[5];
    const float* vw   = (const float*)d_in[6];
    const float* vb   = (const float*)d_in[7];
    float* out = (float*)d_out;

    int V = in_sizes[0] / 64;
    int E = in_sizes[1];
    if (V > MAXV) V = MAXV;
    if (E > MAXE) E = MAXE;

    int nbV = (V + 1023) / 1024;

    k_zero<<<(V + 255) / 256, 256>>>(V);
    k_hist<<<(E + 255) / 256, 256>>>(esrc, E);
    k_scan_block<<<nbV, 1024>>>(V);
    k_scan_partials<<<1, 32>>>(nbV);
    k_scan_add<<<nbV, 1024>>>(V);
    k_scatter<<<(E + 255) / 256, 256>>>(esrc, edst, ew, E);
    k_xu<<<(V + 255) / 256, 256>>>(data, vu, V);
    k_edge<<<(V + 7) / 8, 256>>>(data, vc, V);
    k_gemm<<<(V + 127) / 128, 256>>>(vw, vb, out, V);
}

// round 3
// speedup vs baseline: 1.1285x; 1.1285x over previous
#include <cuda_runtime.h>
#include <cuda_bf16.h>

#define FULL 0xffffffffu

constexpr int MAXV = 100000;
constexpr int MAXE = 1200000;
constexpr int AGG_ROWS = ((MAXV + 255) / 256) * 256;   // 100096 rows capacity

__device__ float g_xu[MAXV * 8];
__device__ int   g_count[MAXV];
__device__ int   g_starts[MAXV];
__device__ int   g_cursor[MAXV];
__device__ int   g_partials[128];
__device__ int   g_pprefix[128];
__device__ int   g_sdst[MAXE];
__device__ float g_sw[MAXE];

// agg rows, bf16 hi/lo, plain row-major [row][k=0..511]
__device__ __align__(16) unsigned char g_aggh[(long long)AGG_ROWS * 1024];
__device__ __align__(16) unsigned char g_aggl[(long long)AGG_ROWS * 1024];
// W packed in mma.m16n8k16 B-fragment order: [kch 0..31][nt 0..7][lane 0..31][reg 0..1] u32
__device__ __align__(16) unsigned g_wh[32 * 8 * 32 * 2];
__device__ __align__(16) unsigned g_wl[32 * 8 * 32 * 2];

// ---------------- counting sort of edges by src ----------------

__global__ void k_zero(int V) {
    int i = blockIdx.x * blockDim.x + threadIdx.x;
    if (i < V) g_count[i] = 0;
}

__global__ void k_hist(const int* __restrict__ src, int E) {
    int e = blockIdx.x * blockDim.x + threadIdx.x;
    if (e < E) atomicAdd(&g_count[src[e]], 1);
}

__global__ void k_scan_block(int V) {
    __shared__ int s[1024];
    int t = threadIdx.x;
    int i = blockIdx.x * 1024 + t;
    int v = (i < V) ? g_count[i] : 0;
    s[t] = v;
    __syncthreads();
    #pragma unroll
    for (int off = 1; off < 1024; off <<= 1) {
        int add = (t >= off) ? s[t - off] : 0;
        __syncthreads();
        s[t] += add;
        __syncthreads();
    }
    if (i < V) g_starts[i] = s[t] - v;
    if (t == 1023) g_partials[blockIdx.x] = s[1023];
}

__global__ void k_scan_partials(int nb) {
    __shared__ int s[128];
    int t = threadIdx.x;
    int v = (t < nb) ? g_partials[t] : 0;
    s[t] = v;
    __syncthreads();
    #pragma unroll
    for (int off = 1; off < 128; off <<= 1) {
        int add = (t >= off) ? s[t - off] : 0;
        __syncthreads();
        s[t] += add;
        __syncthreads();
    }
    if (t < nb) g_pprefix[t] = s[t] - v;
}

__global__ void k_scan_add(int V) {
    int t = threadIdx.x;
    int i = blockIdx.x * 1024 + t;
    if (i < V) {
        int s = g_starts[i] + g_pprefix[blockIdx.x];
        g_starts[i] = s;
        g_cursor[i] = s;
    }
}

__global__ void k_scatter(const int* __restrict__ src, const int* __restrict__ dst,
                          const float* __restrict__ w, int E) {
    int e = blockIdx.x * blockDim.x + threadIdx.x;
    if (e < E) {
        int p = atomicAdd(&g_cursor[src[e]], 1);
        g_sdst[p] = dst[e];
        g_sw[p]   = w[e];
    }
}

// ---------------- xu = data @ var_u  [V,8] ----------------

__global__ void k_xu(const float* __restrict__ data, const float* __restrict__ u, int V) {
    __shared__ float us[512];
    int t = threadIdx.x;
    us[t] = u[t];
    us[t + 256] = u[t + 256];
    __syncthreads();
    int v = blockIdx.x * 256 + t;
    if (v >= V) return;
    float s[8];
    #pragma unroll
    for (int j = 0; j < 8; j++) s[j] = 0.f;
    const float4* row = (const float4*)(data + (long long)v * 64);
    #pragma unroll
    for (int c4 = 0; c4 < 16; c4++) {
        float4 x = row[c4];
        float xs4[4] = {x.x, x.y, x.z, x.w};
        #pragma unroll
        for (int k = 0; k < 4; k++) {
            int c = c4 * 4 + k;
            #pragma unroll
            for (int j = 0; j < 8; j++) s[j] = fmaf(xs4[k], us[c * 8 + j], s[j]);
        }
    }
    #pragma unroll
    for (int j = 0; j < 8; j++) g_xu[v * 8 + j] = s[j];
}

// ---------------- W prep: pack into B-fragment order, bf16 hi/lo ----------------
// W logical: [k=0..511][n=0..63], k = m*64 + c, n = o.  vw flat = vw[k*64 + n].
// B frag (m16n8k16): elem (k,n): lane = (n&7)*4 + ((k&7)>>1), reg = (k>>3)&1, half = k&1.

__global__ void k_wprep(const float* __restrict__ vw) {
    int i = blockIdx.x * 256 + threadIdx.x;   // 0 .. 16383
    if (i >= 256 * 64) return;
    int kp = i >> 6;          // k-pair index: k = 2*kp, 2*kp+1
    int n  = i & 63;
    int k  = kp * 2;
    float w0 = vw[k * 64 + n];
    float w1 = vw[(k + 1) * 64 + n];
    __nv_bfloat16 h0 = __float2bfloat16(w0);
    __nv_bfloat16 h1 = __float2bfloat16(w1);
    __nv_bfloat16 l0 = __float2bfloat16(w0 - __bfloat162float(h0));
    __nv_bfloat16 l1 = __float2bfloat16(w1 - __bfloat162float(h1));
    int kch  = kp >> 3;
    int nt   = n >> 3;
    int lane = (n & 7) * 4 + (kp & 3);
    int reg  = (kp >> 2) & 1;
    int idx  = ((kch * 8 + nt) * 32 + lane) * 2 + reg;
    __nv_bfloat162 ph = __halves2bfloat162(h0, h1);
    __nv_bfloat162 pl = __halves2bfloat162(l0, l1);
    g_wh[idx] = *(unsigned*)&ph;
    g_wl[idx] = *(unsigned*)&pl;
}

// ---------------- per-vertex edge aggregation (warp per vertex) ----------------

__global__ void k_edge(const float* __restrict__ data, const float* __restrict__ cvec, int V) {
    int gw   = (blockIdx.x * blockDim.x + threadIdx.x) >> 5;
    int lane = threadIdx.x & 31;
    if (gw >= V) return;
    int v = gw;

    float xsc = 0.f;
    if (lane < 8) xsc = g_xu[v * 8 + lane] + cvec[lane];

    int beg = g_starts[v];
    int deg = g_count[v];

    float acc[16];
    #pragma unroll
    for (int i = 0; i < 16; i++) acc[i] = 0.f;

    for (int t = 0; t < deg; t++) {
        int p = beg + t;
        int d = 0; float w = 0.f;
        if (lane == 0) { d = g_sdst[p]; w = g_sw[p]; }
        d = __shfl_sync(FULL, d, 0);
        w = __shfl_sync(FULL, w, 0);

        float logit = 0.f;
        if (lane < 8) logit = xsc - g_xu[d * 8 + lane];
        float mx = logit;
        mx = fmaxf(mx, __shfl_xor_sync(FULL, mx, 4));
        mx = fmaxf(mx, __shfl_xor_sync(FULL, mx, 2));
        mx = fmaxf(mx, __shfl_xor_sync(FULL, mx, 1));
        float ex = __expf(logit - mx);
        float sm = ex;
        sm += __shfl_xor_sync(FULL, sm, 4);
        sm += __shfl_xor_sync(FULL, sm, 2);
        sm += __shfl_xor_sync(FULL, sm, 1);
        float qw = __fdividef(ex, sm) * w;

        float2 xj = *(const float2*)(data + (long long)d * 64 + lane * 2);
        #pragma unroll
        for (int m = 0; m < 8; m++) {
            float qm = __shfl_sync(FULL, qw, m);
            acc[2 * m]     = fmaf(qm, xj.x, acc[2 * m]);
            acc[2 * m + 1] = fmaf(qm, xj.y, acc[2 * m + 1]);
        }
    }

    // write split bf16, row-major, fully coalesced
    #pragma unroll
    for (int m = 0; m < 8; m++) {
        float a0 = acc[2 * m], a1 = acc[2 * m + 1];
        __nv_bfloat16 h0 = __float2bfloat16(a0);
        __nv_bfloat16 h1 = __float2bfloat16(a1);
        __nv_bfloat16 l0 = __float2bfloat16(a0 - __bfloat162float(h0));
        __nv_bfloat16 l1 = __float2bfloat16(a1 - __bfloat162float(h1));
        long long off = ((long long)v * 512 + m * 64 + 2 * lane) * 2;
        __nv_bfloat162 ph = __halves2bfloat162(h0, h1);
        __nv_bfloat162 pl = __halves2bfloat162(l0, l1);
        *(__nv_bfloat162*)(g_aggh + off) = ph;
        *(__nv_bfloat162*)(g_aggl + off) = pl;
    }
}

// ---------------- HMMA GEMM: out[V,64] = agg[V,512] @ Wf[512,64] + b ----------------
// split-bf16 3-term emulation: ah*bh + ah*bl + al*bh, fp32 accum.
// CTA = 256 rows (16 m16-groups), warp w handles groups {w, w+8}, all N=64.

__device__ __forceinline__ unsigned smem_u32(const void* p) {
    unsigned a;
    asm("{ .reg .u64 t; cvta.to.shared.u64 t, %1; cvt.u32.u64 %0, t; }" : "=r"(a) : "l"(p));
    return a;
}

__device__ __forceinline__ void mma_bf16(float c[4], const uint4& a, unsigned b0, unsigned b1) {
    asm volatile(
        "mma.sync.aligned.m16n8k16.row.col.f32.bf16.bf16.f32 "
        "{%0,%1,%2,%3}, {%4,%5,%6,%7}, {%8,%9}, {%0,%1,%2,%3};"
        : "+f"(c[0]), "+f"(c[1]), "+f"(c[2]), "+f"(c[3])
        : "r"(a.x), "r"(a.y), "r"(a.z), "r"(a.w), "r"(b0), "r"(b1));
}

#define LDM_X4(v, addr)                                                          \
    asm volatile("ldmatrix.sync.aligned.m8n8.x4.shared.b16 {%0,%1,%2,%3}, [%4];" \
        : "=r"((v).x), "=r"((v).y), "=r"((v).z), "=r"((v).w) : "r"(addr))

// smem layout: Bh 64KB | Bl 64KB | A double-buffer 2 x (hi 12KB + lo 12KB)
constexpr int SM_BH = 0;
constexpr int SM_BL = 65536;
constexpr int SM_A0 = 131072;          // + buf*24576 + arr*12288 ; row stride 48B
constexpr int SM_TOTAL = 131072 + 2 * 24576;   // 180224

__global__ void __launch_bounds__(256, 1)
k_gemm_mma(const float* __restrict__ bias, float* __restrict__ out, int V) {
    extern __shared__ __align__(16) unsigned char smg[];
    unsigned sbase = smem_u32(smg);
    int tid = threadIdx.x, wid = tid >> 5, lane = tid & 31;
    int row0 = blockIdx.x << 8;

    // prefetch A chunk 0 into buffer 0 (cp.async, 16B each)
    #pragma unroll
    for (int i = 0; i < 4; i++) {
        int chunk = i * 256 + tid;         // 0..1023
        int arr = chunk >> 9;              // 0=hi 1=lo
        int c = chunk & 511;
        int row = c >> 1, half = c & 1;
        const unsigned char* g = (arr ? g_aggl : g_aggh)
            + ((long long)(row0 + row) << 10) + (half << 4);
        unsigned d = sbase + SM_A0 + arr * 12288 + row * 48 + half * 16;
        asm volatile("cp.async.cg.shared.global [%0], [%1], 16;" :: "r"(d), "l"(g));
    }
    asm volatile("cp.async.commit_group;" ::: "memory");

    // stage B (128KB) via plain copies (overlaps with async A)
    {
        const float4* srcH = (const float4*)g_wh;
        const float4* srcL = (const float4*)g_wl;
        float4* dH = (float4*)(smg + SM_BH);
        float4* dL = (float4*)(smg + SM_BL);
        #pragma unroll
        for (int i = 0; i < 16; i++) dH[tid + 256 * i] = srcH[tid + 256 * i];
        #pragma unroll
        for (int i = 0; i < 16; i++) dL[tid + 256 * i] = srcL[tid + 256 * i];
    }

    float c0[8][4], c1[8][4];
    #pragma unroll
    for (int nt = 0; nt < 8; nt++)
        #pragma unroll
        for (int j = 0; j < 4; j++) { c0[nt][j] = 0.f; c1[nt][j] = 0.f; }

    int g0l = wid, g1l = wid + 8;
    int r8 = lane & 7, mat = lane >> 3;
    int rowoff = ((mat & 1) << 3) + r8;
    int coloff = (mat >> 1) << 4;

    #pragma unroll 1
    for (int kch = 0; kch < 32; kch++) {
        int buf = kch & 1;
        if (kch < 31) {
            #pragma unroll
            for (int i = 0; i < 4; i++) {
                int chunk = i * 256 + tid;
                int arr = chunk >> 9;
                int c = chunk & 511;
                int row = c >> 1, half = c & 1;
                const unsigned char* g = (arr ? g_aggl : g_aggh)
                    + ((long long)(row0 + row) << 10) + ((kch + 1) << 5) + (half << 4);
                unsigned d = sbase + SM_A0 + (buf ^ 1) * 24576 + arr * 12288 + row * 48 + half * 16;
                asm volatile("cp.async.cg.shared.global [%0], [%1], 16;" :: "r"(d), "l"(g));
            }
            asm volatile("cp.async.commit_group;" ::: "memory");
            asm volatile("cp.async.wait_group 1;" ::: "memory");
        } else {
            asm volatile("cp.async.wait_group 0;" ::: "memory");
        }
        __syncthreads();

        unsigned aH = sbase + SM_A0 + buf * 24576;
        unsigned aL = aH + 12288;
        uint4 ah0, al0, ah1, al1;
        unsigned adr;
        adr = aH + (g0l * 16 + rowoff) * 48 + coloff; LDM_X4(ah0, adr);
        adr = aL + (g0l * 16 + rowoff) * 48 + coloff; LDM_X4(al0, adr);
        adr = aH + (g1l * 16 + rowoff) * 48 + coloff; LDM_X4(ah1, adr);
        adr = aL + (g1l * 16 + rowoff) * 48 + coloff; LDM_X4(al1, adr);

        const uint2* bh = (const uint2*)(smg + SM_BH) + (kch * 8) * 32 + lane;
        const uint2* bl = (const uint2*)(smg + SM_BL) + (kch * 8) * 32 + lane;
        #pragma unroll
        for (int nt = 0; nt < 8; nt++) {
            uint2 vh = bh[nt * 32];
            uint2 vl = bl[nt * 32];
            mma_bf16(c0[nt], ah0, vh.x, vh.y);
            mma_bf16(c0[nt], ah0, vl.x, vl.y);
            mma_bf16(c0[nt], al0, vh.x, vh.y);
            mma_bf16(c1[nt], ah1, vh.x, vh.y);
            mma_bf16(c1[nt], ah1, vl.x, vl.y);
            mma_bf16(c1[nt], al1, vh.x, vh.y);
        }
        __syncthreads();
    }

    // epilogue: C frag (m16n8): c0,c1 row=lane>>2 cols (lane&3)*2+{0,1}; c2,c3 row+8
    int rA = lane >> 2, cBase = (lane & 3) << 1;
    int vr0 = row0 + g0l * 16, vr1 = row0 + g1l * 16;
    #pragma unroll
    for (int nt = 0; nt < 8; nt++) {
        int col = nt * 8 + cBase;
        float b0 = bias[col], b1 = bias[col + 1];
        int r = vr0 + rA;
        if (r < V) *(float2*)(out + (long long)r * 64 + col) =
            make_float2(c0[nt][0] + b0, c0[nt][1] + b1);
        r = vr0 + rA + 8;
        if (r < V) *(float2*)(out + (long long)r * 64 + col) =
            make_float2(c0[nt][2] + b0, c0[nt][3] + b1);
        r = vr1 + rA;
        if (r < V) *(float2*)(out + (long long)r * 64 + col) =
            make_float2(c1[nt][0] + b0, c1[nt][1] + b1);
        r = vr1 + rA + 8;
        if (r < V) *(float2*)(out + (long long)r * 64 + col) =
            make_float2(c1[nt][2] + b0, c1[nt][3] + b1);
    }
}

// ---------------- launch ----------------

extern "C" void kernel_launch(void* const* d_in, const int* in_sizes, int n_in,
                              void* d_out, int out_size) {
    const float* data = (const float*)d_in[0];
    const int*   esrc = (const int*)  d_in[1];
    const int*   edst = (const int*)  d_in[2];
    const float* ew   = (const float*)d_in[3];
    const float* vu   = (const float*)d_in[4];
    const float* vc   = (const float*)d_in[5];
    const float* vw   = (const float*)d_in[6];
    const float* vb   = (const float*)d_in[7];
    float* out = (float*)d_out;

    int V = in_sizes[0] / 64;
    int E = in_sizes[1];
    if (V > MAXV) V = MAXV;
    if (E > MAXE) E = MAXE;

    int nbV = (V + 1023) / 1024;
    int nblk = (V + 255) / 256;

    cudaFuncSetAttribute(k_gemm_mma, cudaFuncAttributeMaxDynamicSharedMemorySize, SM_TOTAL);

    k_zero<<<(V + 255) / 256, 256>>>(V);
    k_hist<<<(E + 255) / 256, 256>>>(esrc, E);
    k_scan_block<<<nbV, 1024>>>(V);
    k_scan_partials<<<1, 128>>>(nbV);
    k_scan_add<<<nbV, 1024>>>(V);
    k_scatter<<<(E + 255) / 256, 256>>>(esrc, edst, ew, E);
    k_wprep<<<64, 256>>>(vw);
    k_xu<<<(V + 255) / 256, 256>>>(data, vu, V);
    k_edge<<<(V + 7) / 8, 256>>>(data, vc, V);
    k_gemm_mma<<<nblk, 256, SM_TOTAL>>>(vb, out, V);
}

// round 4
// speedup vs baseline: 1.1737x; 1.0401x over previous
#include <cuda_runtime.h>
#include <cuda_bf16.h>

#define FULL 0xffffffffu

constexpr int MAXV = 100000;
constexpr int MAXE = 1200000;
constexpr int AGG_ROWS = ((MAXV + 255) / 256) * 256;   // 100096 rows capacity

__device__ float g_p[MAXV * 8];    // exp(xu + c)
__device__ float g_n[MAXV * 8];    // exp(-xu)
__device__ int   g_count[MAXV];    // zero-init at load; re-zeroed by k_gemm each call
__device__ int   g_starts[MAXV];
__device__ int   g_cursor[MAXV];
__device__ int   g_partials[128];
__device__ int2  g_sedge[MAXE];    // (dst, w bits)

// agg rows, bf16 hi/lo, plain row-major [row][k=0..511]
__device__ __align__(16) unsigned char g_aggh[(long long)AGG_ROWS * 1024];
__device__ __align__(16) unsigned char g_aggl[(long long)AGG_ROWS * 1024];
// W packed in mma.m16n8k16 B-fragment order
__device__ __align__(16) unsigned g_wh[32 * 8 * 32 * 2];
__device__ __align__(16) unsigned g_wl[32 * 8 * 32 * 2];

// ---------------- counting sort of edges by src ----------------

__global__ void k_hist(const int* __restrict__ src, int E) {
    int e = blockIdx.x * blockDim.x + threadIdx.x;
    if (e < E) atomicAdd(&g_count[src[e]], 1);
}

__global__ void k_scan_block(int V) {
    __shared__ int s[1024];
    int t = threadIdx.x;
    int i = blockIdx.x * 1024 + t;
    int v = (i < V) ? g_count[i] : 0;
    s[t] = v;
    __syncthreads();
    #pragma unroll
    for (int off = 1; off < 1024; off <<= 1) {
        int add = (t >= off) ? s[t - off] : 0;
        __syncthreads();
        s[t] += add;
        __syncthreads();
    }
    if (i < V) g_starts[i] = s[t] - v;
    if (t == 1023) g_partials[blockIdx.x] = s[1023];
}

// merged: add prefix of partials + init cursor
__global__ void k_scan_add2(int V, int nb) {
    __shared__ int sp[128];
    __shared__ int offs;
    int t = threadIdx.x;
    if (t < 128) sp[t] = (t < nb) ? g_partials[t] : 0;
    __syncthreads();
    if (t < 32) {
        int acc = 0;
        for (int i = t; i < blockIdx.x; i += 32) acc += sp[i];
        #pragma unroll
        for (int o = 16; o; o >>= 1) acc += __shfl_xor_sync(FULL, acc, o);
        if (t == 0) offs = acc;
    }
    __syncthreads();
    int i = blockIdx.x * 1024 + t;
    if (i < V) {
        int s = g_starts[i] + offs;
        g_starts[i] = s;
        g_cursor[i] = s;
    }
}

__global__ void k_scatter(const int* __restrict__ src, const int* __restrict__ dst,
                          const float* __restrict__ w, int E) {
    int e = blockIdx.x * blockDim.x + threadIdx.x;
    if (e < E) {
        int p = atomicAdd(&g_cursor[src[e]], 1);
        g_sedge[p] = make_int2(dst[e], __float_as_int(w[e]));
    }
}

// ---------------- xu = data @ var_u, then P = exp(xu+c), N = exp(-xu) ----------------

__global__ void k_xu(const float* __restrict__ data, const float* __restrict__ u,
                     const float* __restrict__ cvec, int V) {
    __shared__ float us[512];
    __shared__ float cs[8];
    int t = threadIdx.x;
    us[t] = u[t];
    us[t + 256] = u[t + 256];
    if (t < 8) cs[t] = cvec[t];
    __syncthreads();
    int v = blockIdx.x * 256 + t;
    if (v >= V) return;
    float s[8];
    #pragma unroll
    for (int j = 0; j < 8; j++) s[j] = 0.f;
    const float4* row = (const float4*)(data + (long long)v * 64);
    #pragma unroll
    for (int c4 = 0; c4 < 16; c4++) {
        float4 x = row[c4];
        float xs4[4] = {x.x, x.y, x.z, x.w};
        #pragma unroll
        for (int k = 0; k < 4; k++) {
            int c = c4 * 4 + k;
            #pragma unroll
            for (int j = 0; j < 8; j++) s[j] = fmaf(xs4[k], us[c * 8 + j], s[j]);
        }
    }
    #pragma unroll
    for (int j = 0; j < 8; j++) {
        g_p[v * 8 + j] = __expf(s[j] + cs[j]);
        g_n[v * 8 + j] = __expf(-s[j]);
    }
}

// ---------------- W prep: pack into B-fragment order, bf16 hi/lo ----------------

__global__ void k_wprep(const float* __restrict__ vw) {
    int i = blockIdx.x * 256 + threadIdx.x;   // 0 .. 16383
    if (i >= 256 * 64) return;
    int kp = i >> 6;
    int n  = i & 63;
    int k  = kp * 2;
    float w0 = vw[k * 64 + n];
    float w1 = vw[(k + 1) * 64 + n];
    __nv_bfloat16 h0 = __float2bfloat16(w0);
    __nv_bfloat16 h1 = __float2bfloat16(w1);
    __nv_bfloat16 l0 = __float2bfloat16(w0 - __bfloat162float(h0));
    __nv_bfloat16 l1 = __float2bfloat16(w1 - __bfloat162float(h1));
    int kch  = kp >> 3;
    int nt   = n >> 3;
    int lane = (n & 7) * 4 + (kp & 3);
    int reg  = (kp >> 2) & 1;
    int idx  = ((kch * 8 + nt) * 32 + lane) * 2 + reg;
    __nv_bfloat162 ph = __halves2bfloat162(h0, h1);
    __nv_bfloat162 pl = __halves2bfloat162(l0, l1);
    g_wh[idx] = *(unsigned*)&ph;
    g_wl[idx] = *(unsigned*)&pl;
}

// ---------------- per-vertex edge aggregation (warp per vertex, shuffle-diet) ----------------
// lane owns m-pair = (lane>>3)*2 + {0,1}, c-octet = (lane&7)*8 + 0..7  -> 16 acc regs

__global__ void k_edge(const float* __restrict__ data, int V) {
    int gw   = (blockIdx.x * blockDim.x + threadIdx.x) >> 5;
    int lane = threadIdx.x & 31;
    if (gw >= V) return;
    int v = gw;
    int l7 = lane & 7;
    int m0 = (lane >> 3) << 1;       // 0,2,4,6

    float pv = g_p[v * 8 + l7];
    int beg = g_starts[v];
    int deg = g_count[v];

    float acc0[8], acc1[8];
    #pragma unroll
    for (int i = 0; i < 8; i++) { acc0[i] = 0.f; acc1[i] = 0.f; }

    #pragma unroll 2
    for (int t = 0; t < deg; t++) {
        int2 ed = g_sedge[beg + t];
        int d = ed.x;
        float w = __int_as_float(ed.y);

        float tn = pv * g_n[d * 8 + l7];      // exp(logit) per lane's m
        float sm = tn;
        sm += __shfl_xor_sync(FULL, sm, 1);
        sm += __shfl_xor_sync(FULL, sm, 2);
        sm += __shfl_xor_sync(FULL, sm, 4);
        float ts = tn * __fdividef(w, sm);    // q_m * w

        float qa = __shfl_sync(FULL, ts, m0);
        float qb = __shfl_sync(FULL, ts, m0 + 1);

        const float4* xr = (const float4*)(data + (long long)d * 64 + l7 * 8);
        float4 x0 = xr[0];
        float4 x1 = xr[1];

        acc0[0] = fmaf(qa, x0.x, acc0[0]);  acc1[0] = fmaf(qb, x0.x, acc1[0]);
        acc0[1] = fmaf(qa, x0.y, acc0[1]);  acc1[1] = fmaf(qb, x0.y, acc1[1]);
        acc0[2] = fmaf(qa, x0.z, acc0[2]);  acc1[2] = fmaf(qb, x0.z, acc1[2]);
        acc0[3] = fmaf(qa, x0.w, acc0[3]);  acc1[3] = fmaf(qb, x0.w, acc1[3]);
        acc0[4] = fmaf(qa, x1.x, acc0[4]);  acc1[4] = fmaf(qb, x1.x, acc1[4]);
        acc0[5] = fmaf(qa, x1.y, acc0[5]);  acc1[5] = fmaf(qb, x1.y, acc1[5]);
        acc0[6] = fmaf(qa, x1.z, acc0[6]);  acc1[6] = fmaf(qb, x1.z, acc1[6]);
        acc0[7] = fmaf(qa, x1.w, acc0[7]);  acc1[7] = fmaf(qb, x1.w, acc1[7]);
    }

    // epilogue: write split bf16 rows, k = m*64 + l7*8 + cc
    #pragma unroll
    for (int mm = 0; mm < 2; mm++) {
        const float* a = mm ? acc1 : acc0;
        unsigned hi[4], lo[4];
        #pragma unroll
        for (int j = 0; j < 4; j++) {
            float a0 = a[2 * j], a1 = a[2 * j + 1];
            __nv_bfloat16 h0 = __float2bfloat16(a0);
            __nv_bfloat16 h1 = __float2bfloat16(a1);
            __nv_bfloat16 r0 = __float2bfloat16(a0 - __bfloat162float(h0));
            __nv_bfloat16 r1 = __float2bfloat16(a1 - __bfloat162float(h1));
            __nv_bfloat162 ph = __halves2bfloat162(h0, h1);
            __nv_bfloat162 pl = __halves2bfloat162(r0, r1);
            hi[j] = *(unsigned*)&ph;
            lo[j] = *(unsigned*)&pl;
        }
        long long base = (long long)v * 1024 + (m0 + mm) * 128 + l7 * 16;
        *(uint4*)(g_aggh + base) = make_uint4(hi[0], hi[1], hi[2], hi[3]);
        *(uint4*)(g_aggl + base) = make_uint4(lo[0], lo[1], lo[2], lo[3]);
    }
}

// ---------------- HMMA GEMM (unchanged from round 3) ----------------

__device__ __forceinline__ unsigned smem_u32(const void* p) {
    unsigned a;
    asm("{ .reg .u64 t; cvta.to.shared.u64 t, %1; cvt.u32.u64 %0, t; }" : "=r"(a) : "l"(p));
    return a;
}

__device__ __forceinline__ void mma_bf16(float c[4], const uint4& a, unsigned b0, unsigned b1) {
    asm volatile(
        "mma.sync.aligned.m16n8k16.row.col.f32.bf16.bf16.f32 "
        "{%0,%1,%2,%3}, {%4,%5,%6,%7}, {%8,%9}, {%0,%1,%2,%3};"
        : "+f"(c[0]), "+f"(c[1]), "+f"(c[2]), "+f"(c[3])
        : "r"(a.x), "r"(a.y), "r"(a.z), "r"(a.w), "r"(b0), "r"(b1));
}

#define LDM_X4(v, addr)                                                          \
    asm volatile("ldmatrix.sync.aligned.m8n8.x4.shared.b16 {%0,%1,%2,%3}, [%4];" \
        : "=r"((v).x), "=r"((v).y), "=r"((v).z), "=r"((v).w) : "r"(addr))

constexpr int SM_BH = 0;
constexpr int SM_BL = 65536;
constexpr int SM_A0 = 131072;
constexpr int SM_TOTAL = 131072 + 2 * 24576;

__global__ void __launch_bounds__(256, 1)
k_gemm_mma(const float* __restrict__ bias, float* __restrict__ out, int V) {
    extern __shared__ __align__(16) unsigned char smg[];
    unsigned sbase = smem_u32(smg);
    int tid = threadIdx.x, wid = tid >> 5, lane = tid & 31;
    int row0 = blockIdx.x << 8;

    #pragma unroll
    for (int i = 0; i < 4; i++) {
        int chunk = i * 256 + tid;
        int arr = chunk >> 9;
        int c = chunk & 511;
        int row = c >> 1, half = c & 1;
        const unsigned char* g = (arr ? g_aggl : g_aggh)
            + ((long long)(row0 + row) << 10) + (half << 4);
        unsigned d = sbase + SM_A0 + arr * 12288 + row * 48 + half * 16;
        asm volatile("cp.async.cg.shared.global [%0], [%1], 16;" :: "r"(d), "l"(g));
    }
    asm volatile("cp.async.commit_group;" ::: "memory");

    {
        const float4* srcH = (const float4*)g_wh;
        const float4* srcL = (const float4*)g_wl;
        float4* dH = (float4*)(smg + SM_BH);
        float4* dL = (float4*)(smg + SM_BL);
        #pragma unroll
        for (int i = 0; i < 16; i++) dH[tid + 256 * i] = srcH[tid + 256 * i];
        #pragma unroll
        for (int i = 0; i < 16; i++) dL[tid + 256 * i] = srcL[tid + 256 * i];
    }

    float c0[8][4], c1[8][4];
    #pragma unroll
    for (int nt = 0; nt < 8; nt++)
        #pragma unroll
        for (int j = 0; j < 4; j++) { c0[nt][j] = 0.f; c1[nt][j] = 0.f; }

    int g0l = wid, g1l = wid + 8;
    int r8 = lane & 7, mat = lane >> 3;
    int rowoff = ((mat & 1) << 3) + r8;
    int coloff = (mat >> 1) << 4;

    #pragma unroll 1
    for (int kch = 0; kch < 32; kch++) {
        int buf = kch & 1;
        if (kch < 31) {
            #pragma unroll
            for (int i = 0; i < 4; i++) {
                int chunk = i * 256 + tid;
                int arr = chunk >> 9;
                int c = chunk & 511;
                int row = c >> 1, half = c & 1;
                const unsigned char* g = (arr ? g_aggl : g_aggh)
                    + ((long long)(row0 + row) << 10) + ((kch + 1) << 5) + (half << 4);
                unsigned d = sbase + SM_A0 + (buf ^ 1) * 24576 + arr * 12288 + row * 48 + half * 16;
                asm volatile("cp.async.cg.shared.global [%0], [%1], 16;" :: "r"(d), "l"(g));
            }
            asm volatile("cp.async.commit_group;" ::: "memory");
            asm volatile("cp.async.wait_group 1;" ::: "memory");
        } else {
            asm volatile("cp.async.wait_group 0;" ::: "memory");
        }
        __syncthreads();

        unsigned aH = sbase + SM_A0 + buf * 24576;
        unsigned aL = aH + 12288;
        uint4 ah0, al0, ah1, al1;
        unsigned adr;
        adr = aH + (g0l * 16 + rowoff) * 48 + coloff; LDM_X4(ah0, adr);
        adr = aL + (g0l * 16 + rowoff) * 48 + coloff; LDM_X4(al0, adr);
        adr = aH + (g1l * 16 + rowoff) * 48 + coloff; LDM_X4(ah1, adr);
        adr = aL + (g1l * 16 + rowoff) * 48 + coloff; LDM_X4(al1, adr);

        const uint2* bh = (const uint2*)(smg + SM_BH) + (kch * 8) * 32 + lane;
        const uint2* bl = (const uint2*)(smg + SM_BL) + (kch * 8) * 32 + lane;
        #pragma unroll
        for (int nt = 0; nt < 8; nt++) {
            uint2 vh = bh[nt * 32];
            uint2 vl = bl[nt * 32];
            mma_bf16(c0[nt], ah0, vh.x, vh.y);
            mma_bf16(c0[nt], ah0, vl.x, vl.y);
            mma_bf16(c0[nt], al0, vh.x, vh.y);
            mma_bf16(c1[nt], ah1, vh.x, vh.y);
            mma_bf16(c1[nt], ah1, vl.x, vl.y);
            mma_bf16(c1[nt], al1, vh.x, vh.y);
        }
        __syncthreads();
    }

    int rA = lane >> 2, cBase = (lane & 3) << 1;
    int vr0 = row0 + g0l * 16, vr1 = row0 + g1l * 16;
    #pragma unroll
    for (int nt = 0; nt < 8; nt++) {
        int col = nt * 8 + cBase;
        float b0 = bias[col], b1 = bias[col + 1];
        int r = vr0 + rA;
        if (r < V) *(float2*)(out + (long long)r * 64 + col) =
            make_float2(c0[nt][0] + b0, c0[nt][1] + b1);
        r = vr0 + rA + 8;
        if (r < V) *(float2*)(out + (long long)r * 64 + col) =
            make_float2(c0[nt][2] + b0, c0[nt][3] + b1);
        r = vr1 + rA;
        if (r < V) *(float2*)(out + (long long)r * 64 + col) =
            make_float2(c1[nt][0] + b0, c1[nt][1] + b1);
        r = vr1 + rA + 8;
        if (r < V) *(float2*)(out + (long long)r * 64 + col) =
            make_float2(c1[nt][2] + b0, c1[nt][3] + b1);
    }

    // re-zero g_count for the next replay (runs after k_edge consumed it)
    int gz = blockIdx.x * 256 + tid;
    if (gz < V) g_count[gz] = 0;
}

// ---------------- launch ----------------

extern "C" void kernel_launch(void* const* d_in, const int* in_sizes, int n_in,
                              void* d_out, int out_size) {
    const float* data = (const float*)d_in[0];
    const int*   esrc = (const int*)  d_in[1];
    const int*   edst = (const int*)  d_in[2];
    const float* ew   = (const float*)d_in[3];
    const float* vu   = (const float*)d_in[4];
    const float* vc   = (const float*)d_in[5];
    const float* vw   = (const float*)d_in[6];
    const float* vb   = (const float*)d_in[7];
    float* out = (float*)d_out;

    int V = in_sizes[0] / 64;
    int E = in_sizes[1];
    if (V > MAXV) V = MAXV;
    if (E > MAXE) E = MAXE;

    int nbV = (V + 1023) / 1024;
    int nblk = (V + 255) / 256;

    cudaFuncSetAttribute(k_gemm_mma, cudaFuncAttributeMaxDynamicSharedMemorySize, SM_TOTAL);

    k_hist<<<(E + 255) / 256, 256>>>(esrc, E);                 // idx 0
    k_scan_block<<<nbV, 1024>>>(V);                            // idx 1
    k_scan_add2<<<nbV, 1024>>>(V, nbV);                        // idx 2
    k_scatter<<<(E + 255) / 256, 256>>>(esrc, edst, ew, E);    // idx 3  (profiled)
    k_xu<<<(V + 255) / 256, 256>>>(data, vu, vc, V);           // idx 4
    k_wprep<<<64, 256>>>(vw);                                  // idx 5
    k_edge<<<(V + 7) / 8, 256>>>(data, V);                     // idx 6
    k_gemm_mma<<<nblk, 256, SM_TOTAL>>>(vb, out, V);           // idx 7
}